// round 15
// baseline (speedup 1.0000x reference)
#include <cuda_runtime.h>
#include <cuda_fp16.h>
#include <cstdint>
#include <cstddef>

#define I_DIM 512
#define O_DIM 512
#define KDIM  4096          // I_DIM * 8 degrees
#define TILE_M 64
#define TILE_N 128
#define KC     128          // K elems per chunk (16 i's x 8 degrees)
#define NCHUNK (KDIM / KC)  // 32
#define THREADS 128
#define PITCH  272          // 128 halves (256B) + 16B pad; 68 words -> +4 banks/row

#define COEF_SCALE   1024.0f
#define OUT_SCALE    (1.0f / 1024.0f)

// Transposed, scaled fp16 coefficients: Wh[o][k], k = i*8 + d
__device__ __align__(16) __half g_Wh[(size_t)O_DIM * KDIM];

// ---------------- helpers ----------------
__device__ __forceinline__ uint32_t smem_u32(const void* p) {
    uint32_t a;
    asm("{ .reg .u64 t; cvta.to.shared.u64 t, %1; cvt.u32.u64 %0, t; }"
        : "=r"(a) : "l"(p));
    return a;
}

__device__ __forceinline__ void sts128(uint32_t a, uint32_t v0, uint32_t v1,
                                       uint32_t v2, uint32_t v3) {
    asm volatile("st.shared.v4.b32 [%0], {%1,%2,%3,%4};"
                 :: "r"(a), "r"(v0), "r"(v1), "r"(v2), "r"(v3) : "memory");
}

__device__ __forceinline__ void ldsm4(uint32_t* r, uint32_t addr) {
    asm volatile("ldmatrix.sync.aligned.m8n8.x4.shared.b16 {%0,%1,%2,%3}, [%4];"
                 : "=r"(r[0]), "=r"(r[1]), "=r"(r[2]), "=r"(r[3]) : "r"(addr));
}

// m16n8k16 fp16 MMA, f32 accumulate
__device__ __forceinline__ void mma16(float* c, const uint32_t* a, const uint32_t* b) {
    asm volatile(
        "mma.sync.aligned.m16n8k16.row.col.f32.f16.f16.f32 "
        "{%0,%1,%2,%3}, {%4,%5,%6,%7}, {%8,%9}, {%0,%1,%2,%3};"
        : "+f"(c[0]), "+f"(c[1]), "+f"(c[2]), "+f"(c[3])
        : "r"(a[0]), "r"(a[1]), "r"(a[2]), "r"(a[3]), "r"(b[0]), "r"(b[1]));
}

__device__ __forceinline__ uint32_t pack_h2(float lo, float hi) {
    __half2 h = __floats2half2_rn(lo, hi);
    return *reinterpret_cast<uint32_t*>(&h);
}

// accurate-enough tanh: 1 - 2/(exp(2x)+1); MUFU-based, err ~1e-6
__device__ __forceinline__ float fast_tanh(float x) {
    float e = __expf(2.0f * x);
    return 1.0f - __fdividef(2.0f, e + 1.0f);
}

// ---------------- kernel 0: transpose + scale coeffs to fp16 ----------------
__global__ void prep_kernel(const float* __restrict__ coeffs) {
    int idx = blockIdx.x * blockDim.x + threadIdx.x;   // coalesced read
    int i = idx >> 12;
    int o = (idx >> 3) & 511;
    int d = idx & 7;
    g_Wh[((size_t)o << 12) + (i << 3) + d] =
        __float2half_rn(coeffs[idx] * COEF_SCALE);
}

// ---------------- kernel 1: fused poly + fp16 mma GEMM, fine-grained tiles --
// A stage = 64*272 = 17408 B, B stage = 128*272 = 34816 B; double buffered
#define ST_A 17408u
#define ST_B 34816u
#define SMEM_BYTES (2 * (17408 + 34816))   // 104448

__global__ void __launch_bounds__(THREADS, 2)
gegen_kernel(const float* __restrict__ x, float* __restrict__ out) {
    extern __shared__ __align__(16) char smem[];
    const uint32_t sb = smem_u32(smem);
    const int tid  = threadIdx.x;
    const int lane = tid & 31;
    const int wid  = tid >> 5;
    const int b0 = blockIdx.x * TILE_M;
    const int o0 = blockIdx.y * TILE_N;
    const int wm = (wid & 1) * 32;     // 2 warps in M
    const int wn = (wid >> 1) * 64;    // 2 warps in N

    uint32_t aBase[2], bBase[2];
#pragma unroll
    for (int s = 0; s < 2; s++) {
        aBase[s] = sb + s * ST_A;
        bBase[s] = sb + 2 * ST_A + s * ST_B;
    }

    float acc[2][8][4];
#pragma unroll
    for (int mf = 0; mf < 2; mf++)
#pragma unroll
        for (int nf = 0; nf < 8; nf++)
#pragma unroll
            for (int j = 0; j < 4; j++) acc[mf][nf][j] = 0.0f;

    // ---- ldmatrix per-lane offsets (relative to stage base) ----
    const int a_r = lane & 15;
    const int a_c = (lane >> 4) * 16;
    uint32_t aoff[2];
#pragma unroll
    for (int mf = 0; mf < 2; mf++)
        aoff[mf] = (uint32_t)(wm + mf * 16 + a_r) * PITCH + a_c;
    const int b_r = (lane & 7) + ((lane >> 4) & 1) * 8;
    const int b_c = ((lane >> 3) & 1) * 16;
    uint32_t boff[4];
#pragma unroll
    for (int p = 0; p < 4; p++)
        boff[p] = (uint32_t)(wn + p * 16 + b_r) * PITCH + b_c;

    // ---- producer bases ----
    // A: 2 threads per m-row; half covers 8 i's (= 64 k = 128 B) per chunk
    const int prow = tid >> 1;
    const int half = tid & 1;
    const float* xrow = x + (size_t)(b0 + prow) * I_DIM + half * 8;
    const uint32_t a_sts = prow * PITCH + half * 128;
    // B: 1 thread per o-row; 256 B per chunk = 16 x 16B cp.async
    const __half* wrow = g_Wh + ((size_t)(o0 + tid) << 12);
    const uint32_t b_sts = tid * PITCH;

    auto cp_b = [&](int c, uint32_t bBuf) {
        const __half* src = wrow + c * KC;
#pragma unroll
        for (int j = 0; j < 16; j++) {
            asm volatile("cp.async.cg.shared.global [%0], [%1], 16;"
                         :: "r"(bBuf + b_sts + j * 16), "l"(src + j * 8)
                         : "memory");
        }
        asm volatile("cp.async.commit_group;" ::: "memory");
    };

    auto produce_a = [&](uint32_t aBuf, const float4& x0, const float4& x1) {
        const float xs[8] = {x0.x, x0.y, x0.z, x0.w, x1.x, x1.y, x1.z, x1.w};
#pragma unroll
        for (int ii = 0; ii < 8; ii++) {
            float t  = fast_tanh(xs[ii]);
            float t2 = t + t;
            float c0 = 1.0f, c1 = t2;
            float c2 = fmaf(t2, c1, -c0);
            float c3 = fmaf(t2, c2, -c1);
            float c4 = fmaf(t2, c3, -c2);
            float c5 = fmaf(t2, c4, -c3);
            float c6 = fmaf(t2, c5, -c4);
            float c7 = fmaf(t2, c6, -c5);
            sts128(aBuf + a_sts + ii * 16,
                   pack_h2(c0, c1), pack_h2(c2, c3),
                   pack_h2(c4, c5), pack_h2(c6, c7));
        }
    };

    auto consume = [&](uint32_t aBuf, uint32_t bBuf) {
#pragma unroll
        for (int ks = 0; ks < 8; ks++) {
            const uint32_t koff = ks * 32;
            uint32_t a[2][4], b[4][4];
#pragma unroll
            for (int mf = 0; mf < 2; mf++) ldsm4(a[mf], aBuf + aoff[mf] + koff);
#pragma unroll
            for (int p = 0; p < 4; p++)   ldsm4(b[p], bBuf + boff[p] + koff);
#pragma unroll
            for (int mf = 0; mf < 2; mf++)
#pragma unroll
                for (int nf = 0; nf < 8; nf++)
                    mma16(acc[mf][nf], a[mf], &b[nf >> 1][(nf & 1) * 2]);
        }
    };

    // ---- prologue: fill chunk 0 ----
    // chunk c covers i in [16c, 16c+16); this thread's 8 i's start at 16c+8*half
    float4 xa = *reinterpret_cast<const float4*>(xrow);
    float4 xb = *reinterpret_cast<const float4*>(xrow + 4);
    cp_b(0, bBase[0]);
    produce_a(aBase[0], xa, xb);
    xa = *reinterpret_cast<const float4*>(xrow + 16);     // chunk 1
    xb = *reinterpret_cast<const float4*>(xrow + 20);

    // ---- main loop: sync -> cp_b(c+1) -> consume(c) -> produce_a(c+1) ----
#pragma unroll 1
    for (int c = 0; c < NCHUNK; c++) {
        asm volatile("cp.async.wait_group 0;" ::: "memory");
        __syncthreads();   // chunk c visible; buf (c+1)&1 free

        const int cur = c & 1, nxt = cur ^ 1;
        if (c + 1 < NCHUNK) cp_b(c + 1, bBase[nxt]);

        consume(aBase[cur], bBase[cur]);

        if (c + 1 < NCHUNK) {
            produce_a(aBase[nxt], xa, xb);
            if (c + 2 < NCHUNK) {
                xa = *reinterpret_cast<const float4*>(xrow + (c + 2) * 16);
                xb = *reinterpret_cast<const float4*>(xrow + (c + 2) * 16 + 4);
            }
        }
    }

    // ---- epilogue: scale back and store ----
#pragma unroll
    for (int mf = 0; mf < 2; mf++) {
        const int rbase = b0 + wm + mf * 16 + (lane >> 2);
#pragma unroll
        for (int h = 0; h < 2; h++) {
            float* op = out + (size_t)(rbase + h * 8) * O_DIM
                            + o0 + wn + (lane & 3) * 2;
#pragma unroll
            for (int nf = 0; nf < 8; nf++) {
                float2 v;
                v.x = acc[mf][nf][h * 2]     * OUT_SCALE;
                v.y = acc[mf][nf][h * 2 + 1] * OUT_SCALE;
                *reinterpret_cast<float2*>(op + nf * 8) = v;
            }
        }
    }
}

// ---------------- launch ----------------
extern "C" void kernel_launch(void* const* d_in, const int* in_sizes, int n_in,
                              void* d_out, int out_size) {
    const float* x      = (const float*)d_in[0];
    const float* coeffs = (const float*)d_in[1];
    float* out          = (float*)d_out;

    const int B = in_sizes[0] / I_DIM;   // 16384

    prep_kernel<<<(I_DIM * O_DIM * 8) / 256, 256>>>(coeffs);

    cudaFuncSetAttribute(gegen_kernel,
                         cudaFuncAttributeMaxDynamicSharedMemorySize, SMEM_BYTES);

    dim3 grid(B / TILE_M, O_DIM / TILE_N);   // 256 x 4 = 1024 tasks
    gegen_kernel<<<grid, THREADS, SMEM_BYTES>>>(x, out);
}

// round 16
// speedup vs baseline: 1.5273x; 1.5273x over previous
#include <cuda_runtime.h>
#include <cuda_fp16.h>
#include <cstdint>
#include <cstddef>

#define I_DIM 512
#define O_DIM 512
#define BATCH 16384
#define KDIM  3584          // I_DIM * 7 (d=0 folded into bias)
#define TILE_M 256
#define TILE_N 128
#define KC     128          // K per chunk; 8 k16-steps
#define NCHUNK (KDIM / KC)  // 28
#define THREADS 256
#define PITCH  272          // 128 halves (256B) + 16B pad; 68 words -> +4 banks/row

#define COEF_SCALE   1024.0f
#define OUT_SCALE    (1.0f / 1024.0f)

// Repacked, scaled fp16 coefficients: Wh[o][k'], k' = i*7 + (d-1)
__device__ __align__(16) __half g_Wh[(size_t)O_DIM * KDIM];
// Materialized activations: A[b][k'] = U_{d}(tanh(x[b,i])), d = 1..7
__device__ __align__(16) __half g_A[(size_t)BATCH * KDIM];
// Scaled bias: g_bias[o] = 1024 * sum_i coeffs[i][o][0]
__device__ __align__(16) float g_bias[O_DIM];

// ---------------- helpers ----------------
__device__ __forceinline__ uint32_t smem_u32(const void* p) {
    uint32_t a;
    asm("{ .reg .u64 t; cvta.to.shared.u64 t, %1; cvt.u32.u64 %0, t; }"
        : "=r"(a) : "l"(p));
    return a;
}

__device__ __forceinline__ void ldsm4(uint32_t* r, uint32_t addr) {
    asm volatile("ldmatrix.sync.aligned.m8n8.x4.shared.b16 {%0,%1,%2,%3}, [%4];"
                 : "=r"(r[0]), "=r"(r[1]), "=r"(r[2]), "=r"(r[3]) : "r"(addr));
}

// m16n8k16 fp16 MMA, f32 accumulate
__device__ __forceinline__ void mma16(float* c, const uint32_t* a, const uint32_t* b) {
    asm volatile(
        "mma.sync.aligned.m16n8k16.row.col.f32.f16.f16.f32 "
        "{%0,%1,%2,%3}, {%4,%5,%6,%7}, {%8,%9}, {%0,%1,%2,%3};"
        : "+f"(c[0]), "+f"(c[1]), "+f"(c[2]), "+f"(c[3])
        : "r"(a[0]), "r"(a[1]), "r"(a[2]), "r"(a[3]), "r"(b[0]), "r"(b[1]));
}

__device__ __forceinline__ uint32_t pack_h2(float lo, float hi) {
    __half2 h = __floats2half2_rn(lo, hi);
    return *reinterpret_cast<uint32_t*>(&h);
}

// accurate-enough tanh: 1 - 2/(exp(2x)+1); MUFU-based, err ~1e-6
__device__ __forceinline__ float fast_tanh(float x) {
    float e = __expf(2.0f * x);
    return 1.0f - __fdividef(2.0f, e + 1.0f);
}

// ---------------- kernel 0: merged pre-pass ----------------
// blocks [0, 4096): poly  -> g_A    (1M threads, 8 i's each)
// blocks [4096, 12288): wt -> g_Wh  (2M threads, 1 coeff each)
// blocks [12288, 12352): bias       (512 warps, warp-per-o)
#define BLK_POLY 4096
#define BLK_WT   8192
#define BLK_BIAS 64

__global__ void pre_kernel(const float* __restrict__ x,
                           const float* __restrict__ coeffs) {
    const int blk = blockIdx.x;
    const int tid = threadIdx.x;

    if (blk < BLK_POLY) {
        // ---- poly: thread handles 8 consecutive i's of one batch row ----
        int idx = blk * 256 + tid;           // [0, BATCH*64)
        int b  = idx >> 6;
        int ig = idx & 63;                   // i = ig*8 .. +7
        const float* xp = x + ((size_t)b << 9) + ig * 8;
        float4 xv0 = *reinterpret_cast<const float4*>(xp);
        float4 xv1 = *reinterpret_cast<const float4*>(xp + 4);
        const float xs[8] = {xv0.x, xv0.y, xv0.z, xv0.w,
                             xv1.x, xv1.y, xv1.z, xv1.w};
        float H[56];
#pragma unroll
        for (int p = 0; p < 8; p++) {
            float t  = fast_tanh(xs[p]);
            float t2 = t + t;
            float cm = t2;                       // U1
            float cn = fmaf(t2, cm, -1.0f);      // U2
            H[p * 7 + 0] = cm;
            H[p * 7 + 1] = cn;
#pragma unroll
            for (int n = 2; n < 7; n++) {
                float cx = fmaf(t2, cn, -cm);    // U_{n+1}
                cm = cn; cn = cx;
                H[p * 7 + n] = cx;
            }
        }
        uint32_t U[28];
#pragma unroll
        for (int m = 0; m < 28; m++) U[m] = pack_h2(H[2 * m], H[2 * m + 1]);
        uint4* dst = reinterpret_cast<uint4*>(g_A + (size_t)b * KDIM + ig * 56);
#pragma unroll
        for (int q = 0; q < 7; q++)
            dst[q] = make_uint4(U[q * 4], U[q * 4 + 1], U[q * 4 + 2], U[q * 4 + 3]);
    } else if (blk < BLK_POLY + BLK_WT) {
        // ---- wt repack: k' = i*7 + (d-1), scaled ----
        int e = (blk - BLK_POLY) * 256 + tid;   // (i, o, d), d fastest
        int i = e >> 12;
        int o = (e >> 3) & 511;
        int d = e & 7;
        if (d > 0) {
            g_Wh[(size_t)o * KDIM + i * 7 + (d - 1)] =
                __float2half_rn(coeffs[e] * COEF_SCALE);
        }
    } else {
        // ---- bias: warp-per-o ----
        int wg   = (blk - BLK_POLY - BLK_WT) * 8 + (tid >> 5);  // o = wg
        int lane = tid & 31;
        float s = 0.0f;
#pragma unroll
        for (int r = 0; r < 16; r++) {
            int i = lane + r * 32;
            s += coeffs[(((size_t)i << 9) + wg) << 3];          // (i, o, 0)
        }
#pragma unroll
        for (int off = 16; off > 0; off >>= 1)
            s += __shfl_down_sync(0xFFFFFFFFu, s, off);
        if (lane == 0) g_bias[wg] = s * COEF_SCALE;
    }
}

// ---------------- kernel 1: pure fp16 mma GEMM (K=3584) ----------------
// A stage = 256*272 = 69632 B, B stage = 128*272 = 34816 B; double buffered
#define ST_A 69632u
#define ST_B 34816u
#define SMEM_BYTES (2 * (69632 + 34816))   // 208896

__global__ void __launch_bounds__(THREADS, 1)
gegen_kernel(float* __restrict__ out) {
    extern __shared__ __align__(16) char smem[];
    const uint32_t sb = smem_u32(smem);
    const int tid  = threadIdx.x;
    const int lane = tid & 31;
    const int wid  = tid >> 5;
    const int o0 = blockIdx.x * TILE_N;   // N fastest: co-resident CTAs share A
    const int b0 = blockIdx.y * TILE_M;
    const int wm = (wid & 3) * 64;        // 4 warps in M
    const int wn = (wid >> 2) * 64;       // 2 warps in N

    uint32_t aBase[2], bBase[2];
#pragma unroll
    for (int s = 0; s < 2; s++) {
        aBase[s] = sb + s * ST_A;
        bBase[s] = sb + 2 * ST_A + s * ST_B;
    }

    // ---- accumulators initialized with bias ----
    float acc[4][8][4];
#pragma unroll
    for (int nf = 0; nf < 8; nf++) {
        const float* bp = g_bias + o0 + wn + nf * 8 + (lane & 3) * 2;
        float bx = bp[0], by = bp[1];
#pragma unroll
        for (int mf = 0; mf < 4; mf++) {
            acc[mf][nf][0] = bx; acc[mf][nf][1] = by;
            acc[mf][nf][2] = bx; acc[mf][nf][3] = by;
        }
    }

    // ---- ldmatrix per-lane offsets ----
    const int a_r = lane & 15;
    const int a_c = (lane >> 4) * 16;
    uint32_t aoff[4];
#pragma unroll
    for (int mf = 0; mf < 4; mf++)
        aoff[mf] = (uint32_t)(wm + mf * 16 + a_r) * PITCH + a_c;
    const int b_r = (lane & 7) + ((lane >> 4) & 1) * 8;
    const int b_c = ((lane >> 3) & 1) * 16;
    uint32_t boff[4];
#pragma unroll
    for (int p = 0; p < 4; p++)
        boff[p] = (uint32_t)(wn + p * 16 + b_r) * PITCH + b_c;

    // ---- cp.async mapping: 16 threads per 256B chunk-row ----
    const int crow = tid >> 4;            // 0..15
    const int cseg = tid & 15;            // 16B segment
    const __half* pA = g_A  + (size_t)(b0 + crow) * KDIM + cseg * 8;
    const __half* pB = g_Wh + (size_t)(o0 + crow) * KDIM + cseg * 8;
    const uint32_t dstb = (uint32_t)crow * PITCH + cseg * 16;

    auto issue = [&](int c, uint32_t aBuf, uint32_t bBuf) {
        const size_t koff = (size_t)c * KC;
#pragma unroll
        for (int j = 0; j < 16; j++) {    // A: 256 rows
            asm volatile("cp.async.cg.shared.global [%0], [%1], 16;"
                         :: "r"(aBuf + dstb + j * (16 * PITCH)),
                            "l"(pA + (size_t)j * 16 * KDIM + koff) : "memory");
        }
#pragma unroll
        for (int j = 0; j < 8; j++) {     // B: 128 rows
            asm volatile("cp.async.cg.shared.global [%0], [%1], 16;"
                         :: "r"(bBuf + dstb + j * (16 * PITCH)),
                            "l"(pB + (size_t)j * 16 * KDIM + koff) : "memory");
        }
        asm volatile("cp.async.commit_group;" ::: "memory");
    };

    auto consume = [&](uint32_t aBuf, uint32_t bBuf) {
#pragma unroll
        for (int ks = 0; ks < 8; ks++) {
            const uint32_t koff = ks * 32;
            uint32_t a[4][4], b[4][4];
#pragma unroll
            for (int mf = 0; mf < 4; mf++) ldsm4(a[mf], aBuf + aoff[mf] + koff);
#pragma unroll
            for (int p = 0; p < 4; p++)   ldsm4(b[p], bBuf + boff[p] + koff);
#pragma unroll
            for (int mf = 0; mf < 4; mf++)
#pragma unroll
                for (int nf = 0; nf < 8; nf++)
                    mma16(acc[mf][nf], a[mf], &b[nf >> 1][(nf & 1) * 2]);
        }
    };

    // ---- prologue ----
    issue(0, aBase[0], bBase[0]);

    // ---- main loop: wait -> sync -> issue(c+1) -> consume(c) ----
#pragma unroll 1
    for (int c = 0; c < NCHUNK; c++) {
        asm volatile("cp.async.wait_group 0;" ::: "memory");
        __syncthreads();   // chunk c visible; buf (c+1)&1 free

        const int cur = c & 1, nxt = cur ^ 1;
        if (c + 1 < NCHUNK) issue(c + 1, aBase[nxt], bBase[nxt]);

        consume(aBase[cur], bBase[cur]);
    }

    // ---- epilogue: scale back and store (bias already in acc) ----
#pragma unroll
    for (int mf = 0; mf < 4; mf++) {
        const int rbase = b0 + wm + mf * 16 + (lane >> 2);
#pragma unroll
        for (int h = 0; h < 2; h++) {
            float* op = out + (size_t)(rbase + h * 8) * O_DIM
                            + o0 + wn + (lane & 3) * 2;
#pragma unroll
            for (int nf = 0; nf < 8; nf++) {
                float2 v;
                v.x = acc[mf][nf][h * 2]     * OUT_SCALE;
                v.y = acc[mf][nf][h * 2 + 1] * OUT_SCALE;
                *reinterpret_cast<float2*>(op + nf * 8) = v;
            }
        }
    }
}

// ---------------- launch ----------------
extern "C" void kernel_launch(void* const* d_in, const int* in_sizes, int n_in,
                              void* d_out, int out_size) {
    const float* x      = (const float*)d_in[0];
    const float* coeffs = (const float*)d_in[1];
    float* out          = (float*)d_out;

    const int B = in_sizes[0] / I_DIM;   // 16384

    pre_kernel<<<BLK_POLY + BLK_WT + BLK_BIAS, 256>>>(x, coeffs);

    cudaFuncSetAttribute(gegen_kernel,
                         cudaFuncAttributeMaxDynamicSharedMemorySize, SMEM_BYTES);

    dim3 grid(O_DIM / TILE_N, B / TILE_M);   // 4 x 64: N fastest
    gegen_kernel<<<grid, THREADS, SMEM_BYTES>>>(out);
}